// round 12
// baseline (speedup 1.0000x reference)
#include <cuda_runtime.h>
#include <cuda_bf16.h>
#include <cstdint>
#include <math.h>

#define BB   4
#define LLEN 1024
#define DD   768
#define HH   12
#define NE_  42
#define MM   4
#define PP   512
#define NL_  97
#define NG_  12      // D / BLK
#define NT_  13      // bilinear n-tiles of 8 (97 -> 104)

// ---------------- scratch (static device globals; no runtime allocation) ----
__device__ float g_ent_att[BB*NE_*HH*LLEN];
__device__ float g_hsW[BB*NE_*DD];
__device__ float g_tsW[BB*NE_*DD];
__device__ float g_zs[BB*PP*DD];
__device__ float g_zo[BB*PP*DD];
__device__ float g_part[NG_][BB*PP*NL_];
// pair-split bf16 operands (u32 = 2 adjacent-k bf16)
__device__ uint32_t g_eHi[BB*NE_*DD/2],  g_eLo[BB*NE_*DD/2];    // entity embeds
__device__ uint32_t g_wnHi[BB*PP*LLEN/2], g_wnLo[BB*PP*LLEN/2]; // pair weights
__device__ uint32_t g_rsHi[BB*PP*DD/2],  g_rsLo[BB*PP*DD/2];    // rs (A of zs/zo)
// B fragment arrays: [t][s][lane] uint4 {bhi0,bhi1,blo0,blo1}
__device__ uint4 g_seqF[(size_t)BB*96*64*32];                   // seq per batch (S=64)
__device__ uint4 g_W1hF[96*48*32], g_W1tF[96*48*32];            // W[:768]
__device__ uint4 g_W2hF[96*48*32], g_W2tF[96*48*32];            // W[768:]
// bilinear W fragments: [g][s][t][lane]
__device__ uint4 g_Wfrag[(size_t)NG_*256*NT_*32];

// ---------------- helpers ---------------------------------------------------
__device__ __forceinline__ uint32_t pack_split(float a, float b, uint32_t& lo){
    __nv_bfloat16 ha = __float2bfloat16(a), hb = __float2bfloat16(b);
    float ra = a - __bfloat162float(ha);
    float rb = b - __bfloat162float(hb);
    __nv_bfloat16 la = __float2bfloat16(ra), lb = __float2bfloat16(rb);
    lo = (uint32_t)__bfloat16_as_ushort(la) | ((uint32_t)__bfloat16_as_ushort(lb) << 16);
    return (uint32_t)__bfloat16_as_ushort(ha) | ((uint32_t)__bfloat16_as_ushort(hb) << 16);
}
__device__ __forceinline__ void mma16816(float* d,
    uint32_t a0, uint32_t a1, uint32_t a2, uint32_t a3,
    uint32_t b0, uint32_t b1){
    asm volatile("mma.sync.aligned.m16n8k16.row.col.f32.bf16.bf16.f32 "
        "{%0,%1,%2,%3}, {%4,%5,%6,%7}, {%8,%9}, {%0,%1,%2,%3};\n"
        : "+f"(d[0]), "+f"(d[1]), "+f"(d[2]), "+f"(d[3])
        : "r"(a0), "r"(a1), "r"(a2), "r"(a3), "r"(b0), "r"(b1));
}

// ---------------- kernel 1: entity embeddings -> split pairs ----------------
__global__ void k_ent_emb(const float* __restrict__ seq, const int* __restrict__ mpos){
    int be = blockIdx.x;
    int b  = be / NE_;
    const int* mp = mpos + be*MM;
    int p0 = mp[0]+1, p1 = mp[1]+1, p2 = mp[2]+1, p3 = mp[3]+1;
    const float* s = seq + (size_t)b*LLEN*DD;
    for (int d2 = threadIdx.x; d2 < DD/2; d2 += blockDim.x){
        float v[2];
        #pragma unroll
        for (int e = 0; e < 2; ++e){
            int d = 2*d2 + e;
            float v0 = s[(size_t)p0*DD+d], v1 = s[(size_t)p1*DD+d];
            float v2 = s[(size_t)p2*DD+d], v3 = s[(size_t)p3*DD+d];
            float mx = fmaxf(fmaxf(v0,v1), fmaxf(v2,v3));
            float sm = expf(v0-mx)+expf(v1-mx)+expf(v2-mx)+expf(v3-mx);
            v[e] = mx + logf(sm);
        }
        uint32_t lo; uint32_t hi = pack_split(v[0], v[1], lo);
        g_eHi[(size_t)be*(DD/2) + d2] = hi;
        g_eLo[(size_t)be*(DD/2) + d2] = lo;
    }
}

// ---------------- kernel 2: entity attention rows ---------------------------
__global__ void k_ent_att(const float* __restrict__ att, const int* __restrict__ mpos){
    int beh = blockIdx.x;
    int h   = beh % HH;
    int be  = beh / HH;
    int b   = be / NE_;
    const int* mp = mpos + be*MM;
    int p0 = mp[0]+1, p1 = mp[1]+1, p2 = mp[2]+1, p3 = mp[3]+1;
    const float* A = att + ((size_t)(b*HH + h))*LLEN*LLEN;
    float* out = g_ent_att + ((size_t)be*HH + h)*LLEN;
    for (int l = threadIdx.x; l < LLEN; l += blockDim.x){
        float v = A[(size_t)p0*LLEN+l] + A[(size_t)p1*LLEN+l]
                + A[(size_t)p2*LLEN+l] + A[(size_t)p3*LLEN+l];
        out[l] = v * 0.25f;
    }
}

// ---------------- kernel 3: pair weights -> split pairs ---------------------
__global__ void k_pairw(const int* __restrict__ hts){
    int bp = blockIdx.x;
    int b  = bp >> 9;
    int hi_ = hts[bp*2+0], ti = hts[bp*2+1];
    __shared__ float sd[LLEN];
    __shared__ float red[8];
    const float* Ah = g_ent_att + ((size_t)(b*NE_ + hi_))*HH*LLEN;
    const float* At = g_ent_att + ((size_t)(b*NE_ + ti))*HH*LLEN;
    float lsum = 0.f;
    for (int l = threadIdx.x; l < LLEN; l += blockDim.x){
        float s = 0.f;
        #pragma unroll
        for (int h = 0; h < HH; ++h) s += Ah[h*LLEN+l]*At[h*LLEN+l];
        sd[l] = s; lsum += s;
    }
    #pragma unroll
    for (int o = 16; o; o >>= 1) lsum += __shfl_xor_sync(0xFFFFFFFFu, lsum, o);
    if ((threadIdx.x & 31) == 0) red[threadIdx.x >> 5] = lsum;
    __syncthreads();
    float total = red[0]+red[1]+red[2]+red[3]+red[4]+red[5]+red[6]+red[7];
    float inv = 1.f / (total + (float)HH*1e-5f);
    for (int l2 = threadIdx.x; l2 < LLEN/2; l2 += blockDim.x){
        uint32_t lo; uint32_t hi = pack_split(sd[2*l2]*inv, sd[2*l2+1]*inv, lo);
        g_wnHi[(size_t)bp*(LLEN/2) + l2] = hi;
        g_wnLo[(size_t)bp*(LLEN/2) + l2] = lo;
    }
}

// ---------------- pack B operand [16s x 768n] fp32 -> mma fragments ---------
// grid (S, batches), 128 thr; dst[((t*S + s)*32 + lane] uint4
__global__ void __launch_bounds__(128) k_packB(const float* __restrict__ src, long sSrc,
                                               uint4* __restrict__ dst, long sDst, int S){
    __shared__ float w_sh[16*768];
    int tid = threadIdx.x;
    int s = blockIdx.x;
    const float* s0 = src + (size_t)blockIdx.y*sSrc + (size_t)s*16*768;
    for (int idx = tid; idx < 16*768; idx += 128) w_sh[idx] = s0[idx];
    __syncthreads();
    uint4* d0 = dst + (size_t)blockIdx.y*sDst;
    for (int e = tid; e < 96*32; e += 128){
        int t = e >> 5, lane = e & 31;
        int gid = lane >> 2, q = lane & 3;
        int n = t*8 + gid, k0 = q*2;
        uint32_t l0, l1; uint4 F;
        F.x = pack_split(w_sh[k0*768+n],     w_sh[(k0+1)*768+n], l0);
        F.y = pack_split(w_sh[(k0+8)*768+n], w_sh[(k0+9)*768+n], l1);
        F.z = l0; F.w = l1;
        d0[((size_t)t*S + s)*32 + lane] = F;
    }
}

// ---------------- unified HMMA bf16x3 GEMM ----------------------------------
// CTA 64m x 128n, 8 warps (4m x 2n), warp m16 x n64. A from pair arrays, B frags.
__global__ void __launch_bounds__(256) k_hgemm(
    const uint32_t* __restrict__ Ahi, const uint32_t* __restrict__ Alo, long sA,
    const uint4* __restrict__ Bf, long sB,
    float* __restrict__ Cout,
    uint32_t* __restrict__ CpHi, uint32_t* __restrict__ CpLo,
    int Mr, int S,
    const float* __restrict__ bias,
    const float* __restrict__ eW,
    const int* __restrict__ hts, int which)
{
    int tid = threadIdx.x, lane = tid & 31, wid = tid >> 5;
    int pb = wid >> 1, nh = wid & 1, gid = lane >> 2, q = lane & 3;
    int z = blockIdx.z;
    int Kd2 = S*8;
    const uint32_t* AH = Ahi + (size_t)z*sA;
    const uint32_t* AL = Alo + (size_t)z*sA;
    int nt0 = blockIdx.x*16 + nh*8;
    const uint4* BF = Bf + (size_t)z*sB + ((size_t)nt0*S)*32 + lane;

    int row0 = blockIdx.y*64 + pb*16 + gid;
    int row8 = row0 + 8;
    int rc0 = min(row0, Mr-1), rc8 = min(row8, Mr-1);
    const uint32_t* ah0 = AH + (size_t)rc0*Kd2;
    const uint32_t* ah8 = AH + (size_t)rc8*Kd2;
    const uint32_t* al0 = AL + (size_t)rc0*Kd2;
    const uint32_t* al8 = AL + (size_t)rc8*Kd2;

    float acc[8][4];
    #pragma unroll
    for (int tt = 0; tt < 8; ++tt){
        acc[tt][0]=0.f; acc[tt][1]=0.f; acc[tt][2]=0.f; acc[tt][3]=0.f;
    }

    for (int s = 0; s < S; ++s){
        int i0 = s*8 + q, i1 = s*8 + 4 + q;
        uint32_t Ah0 = ah0[i0], Ah2 = ah0[i1];
        uint32_t Ah1 = ah8[i0], Ah3 = ah8[i1];
        uint32_t Al0 = al0[i0], Al2 = al0[i1];
        uint32_t Al1 = al8[i0], Al3 = al8[i1];
        #pragma unroll
        for (int tt = 0; tt < 8; ++tt){
            uint4 B = BF[((size_t)tt*S + s)*32];
            mma16816(acc[tt], Ah0,Ah1,Ah2,Ah3, B.x, B.y);   // hi*hi
            mma16816(acc[tt], Ah0,Ah1,Ah2,Ah3, B.z, B.w);   // hi*lo
            mma16816(acc[tt], Al0,Al1,Al2,Al3, B.x, B.y);   // lo*hi
        }
    }

    int crow0 = z*Mr + row0, crow8 = z*Mr + row8;
    const float *ev0 = 0, *ev8 = 0;
    if (eW){
        ev0 = eW + ((size_t)((crow0 >> 9)*NE_ + hts[crow0*2 + which]))*DD;
        ev8 = eW + ((size_t)((crow8 >> 9)*NE_ + hts[crow8*2 + which]))*DD;
    }
    int nbase = nt0*8;
    #pragma unroll
    for (int tt = 0; tt < 8; ++tt){
        int n0 = nbase + tt*8 + q*2;
        float v0 = acc[tt][0], v1 = acc[tt][1], v2 = acc[tt][2], v3 = acc[tt][3];
        if (eW){
            v0 = tanhf(v0 + ev0[n0]   + bias[n0]);
            v1 = tanhf(v1 + ev0[n0+1] + bias[n0+1]);
            v2 = tanhf(v2 + ev8[n0]   + bias[n0]);
            v3 = tanhf(v3 + ev8[n0+1] + bias[n0+1]);
        }
        if (Cout){
            if (row0 < Mr) *(float2*)&Cout[(size_t)crow0*DD + n0] = make_float2(v0, v1);
            if (row8 < Mr) *(float2*)&Cout[(size_t)crow8*DD + n0] = make_float2(v2, v3);
        }
        if (CpHi){
            uint32_t lo0, lo8;
            uint32_t hi0 = pack_split(v0, v1, lo0);
            uint32_t hi8 = pack_split(v2, v3, lo8);
            if (row0 < Mr){
                CpHi[(size_t)crow0*(DD/2) + (n0>>1)] = hi0;
                CpLo[(size_t)crow0*(DD/2) + (n0>>1)] = lo0;
            }
            if (row8 < Mr){
                CpHi[(size_t)crow8*(DD/2) + (n0>>1)] = hi8;
                CpLo[(size_t)crow8*(DD/2) + (n0>>1)] = lo8;
            }
        }
    }
}

// ---------------- prep: W_bi -> per-thread mma B fragments ------------------
__global__ void __launch_bounds__(128) k_prepW(const float* __restrict__ Wbi){
    int bid = blockIdx.x;
    int g = bid >> 8, s = bid & 255;
    __shared__ float w_sh[16][104];
    int tid = threadIdx.x;
    for (int idx = tid; idx < 16*104; idx += 128){
        int r = idx / 104, n = idx - r*104;
        w_sh[r][n] = (n < NL_) ? Wbi[(size_t)(g*4096 + s*16 + r)*NL_ + n] : 0.f;
    }
    __syncthreads();
    for (int e = tid; e < NT_*32; e += 128){
        int t = e >> 5, lane = e & 31;
        int gid = lane >> 2, q = lane & 3;
        int n = t*8 + gid;
        int k0 = q*2;
        float w0 = w_sh[k0][n],   w1 = w_sh[k0+1][n];
        float w2 = w_sh[k0+8][n], w3 = w_sh[k0+9][n];
        uint4 F; uint32_t l0, l1;
        F.x = pack_split(w0, w1, l0);
        F.y = pack_split(w2, w3, l1);
        F.z = l0; F.w = l1;
        g_Wfrag[(((size_t)g*256 + s)*NT_ + t)*32 + lane] = F;
    }
}

// ---------------- HMMA bf16-split grouped bilinear --------------------------
__global__ void __launch_bounds__(256,2) k_bilinear(){
    __shared__ float zs_sh[64*65];
    __shared__ float zo_sh[64*65];
    int tid = threadIdx.x, lane = tid & 31, wid = tid >> 5;
    int pb = wid >> 1, nh = wid & 1;
    int g  = blockIdx.y;
    int p0 = blockIdx.x * 64;

    for (int idx = tid; idx < 64*16; idx += 256){
        int p = idx >> 4, c4 = idx & 15;
        float4 vs = *(const float4*)(g_zs + (size_t)(p0+p)*DD + g*64 + c4*4);
        float4 vo = *(const float4*)(g_zo + (size_t)(p0+p)*DD + g*64 + c4*4);
        zs_sh[p*65 + c4*4+0] = vs.x; zs_sh[p*65 + c4*4+1] = vs.y;
        zs_sh[p*65 + c4*4+2] = vs.z; zs_sh[p*65 + c4*4+3] = vs.w;
        zo_sh[p*65 + c4*4+0] = vo.x; zo_sh[p*65 + c4*4+1] = vo.y;
        zo_sh[p*65 + c4*4+2] = vo.z; zo_sh[p*65 + c4*4+3] = vo.w;
    }
    __syncthreads();

    int gid = lane >> 2, q = lane & 3;
    int r0 = pb*16 + gid, r8 = r0 + 8;
    int t0 = nh * 6;
    const uint4* bbase = g_Wfrag + (((size_t)g*256)*NT_ + t0)*32 + lane;

    float acc[7][4];
    #pragma unroll
    for (int tt = 0; tt < 7; ++tt){
        acc[tt][0] = 0.f; acc[tt][1] = 0.f; acc[tt][2] = 0.f; acc[tt][3] = 0.f;
    }

    for (int s = 0; s < 256; ++s){
        uint4 Bf[7];
        const uint4* bp = bbase + (size_t)s*(NT_*32);
        #pragma unroll
        for (int tt = 0; tt < 7; ++tt) Bf[tt] = bp[tt*32];

        int i  = s >> 2;
        int c0 = ((s & 3) << 4) + q*2;
        float zr0 = zs_sh[r0*65 + i], zr8 = zs_sh[r8*65 + i];
        float o00 = zo_sh[r0*65 + c0],   o01 = zo_sh[r0*65 + c0+1];
        float o08 = zo_sh[r0*65 + c0+8], o09 = zo_sh[r0*65 + c0+9];
        float o80 = zo_sh[r8*65 + c0],   o81 = zo_sh[r8*65 + c0+1];
        float o88 = zo_sh[r8*65 + c0+8], o89 = zo_sh[r8*65 + c0+9];
        uint32_t al0, al1, al2, al3;
        uint32_t ah0 = pack_split(zr0*o00, zr0*o01, al0);
        uint32_t ah1 = pack_split(zr8*o80, zr8*o81, al1);
        uint32_t ah2 = pack_split(zr0*o08, zr0*o09, al2);
        uint32_t ah3 = pack_split(zr8*o88, zr8*o89, al3);

        #pragma unroll
        for (int tt = 0; tt < 7; ++tt){
            mma16816(acc[tt], ah0, ah1, ah2, ah3, Bf[tt].x, Bf[tt].y);
            mma16816(acc[tt], ah0, ah1, ah2, ah3, Bf[tt].z, Bf[tt].w);
            mma16816(acc[tt], al0, al1, al2, al3, Bf[tt].x, Bf[tt].y);
        }
    }

    int row0g = p0 + r0, row8g = p0 + r8;
    #pragma unroll
    for (int tt = 0; tt < 7; ++tt){
        int n0 = (t0 + tt)*8 + q*2;
        if (n0 < NL_){
            g_part[g][(size_t)row0g*NL_ + n0] = acc[tt][0];
            g_part[g][(size_t)row8g*NL_ + n0] = acc[tt][2];
        }
        if (n0 + 1 < NL_){
            g_part[g][(size_t)row0g*NL_ + n0+1] = acc[tt][1];
            g_part[g][(size_t)row8g*NL_ + n0+1] = acc[tt][3];
        }
    }
}

// ---------------- finish: sum 12 partials + bias ----------------------------
__global__ void k_finish(float* __restrict__ out, const float* __restrict__ b_bi){
    int i = blockIdx.x*blockDim.x + threadIdx.x;
    if (i < BB*PP*NL_){
        float s = b_bi[i % NL_];
        #pragma unroll
        for (int q = 0; q < NG_; ++q) s += g_part[q][i];
        out[i] = s;
    }
}

// ---------------- launch ----------------------------------------------------
extern "C" void kernel_launch(void* const* d_in, const int* in_sizes, int n_in,
                              void* d_out, int out_size){
    const float* seq  = (const float*)d_in[0];
    const float* att  = (const float*)d_in[1];
    const int*   mpos = (const int*)  d_in[2];
    const int*   hts  = (const int*)  d_in[3];
    const float* Wh   = (const float*)d_in[4];
    const float* bh   = (const float*)d_in[5];
    const float* Wt   = (const float*)d_in[6];
    const float* bt   = (const float*)d_in[7];
    const float* Wbi  = (const float*)d_in[8];
    const float* bbi  = (const float*)d_in[9];
    float* out = (float*)d_out;

    float *p_hsW, *p_tsW, *p_zs, *p_zo;
    uint32_t *p_eHi, *p_eLo, *p_wnHi, *p_wnLo, *p_rsHi, *p_rsLo;
    uint4 *p_seqF, *p_W1hF, *p_W1tF, *p_W2hF, *p_W2tF;
    cudaGetSymbolAddress((void**)&p_hsW,  g_hsW);
    cudaGetSymbolAddress((void**)&p_tsW,  g_tsW);
    cudaGetSymbolAddress((void**)&p_zs,   g_zs);
    cudaGetSymbolAddress((void**)&p_zo,   g_zo);
    cudaGetSymbolAddress((void**)&p_eHi,  g_eHi);
    cudaGetSymbolAddress((void**)&p_eLo,  g_eLo);
    cudaGetSymbolAddress((void**)&p_wnHi, g_wnHi);
    cudaGetSymbolAddress((void**)&p_wnLo, g_wnLo);
    cudaGetSymbolAddress((void**)&p_rsHi, g_rsHi);
    cudaGetSymbolAddress((void**)&p_rsLo, g_rsLo);
    cudaGetSymbolAddress((void**)&p_seqF, g_seqF);
    cudaGetSymbolAddress((void**)&p_W1hF, g_W1hF);
    cudaGetSymbolAddress((void**)&p_W1tF, g_W1tF);
    cudaGetSymbolAddress((void**)&p_W2hF, g_W2hF);
    cudaGetSymbolAddress((void**)&p_W2tF, g_W2tF);

    // operand prep (independent of each other)
    k_prepW<<<NG_*256, 128>>>(Wbi);
    k_packB<<<dim3(64, BB), 128>>>(seq, (long)LLEN*DD, p_seqF, (long)96*64*32, 64);
    k_packB<<<dim3(48, 1), 128>>>(Wh,               0, p_W1hF, 0, 48);
    k_packB<<<dim3(48, 1), 128>>>(Wt,               0, p_W1tF, 0, 48);
    k_packB<<<dim3(48, 1), 128>>>(Wh + (size_t)DD*DD, 0, p_W2hF, 0, 48);
    k_packB<<<dim3(48, 1), 128>>>(Wt + (size_t)DD*DD, 0, p_W2tF, 0, 48);

    k_ent_emb<<<BB*NE_, 256>>>(seq, mpos);
    k_ent_att<<<BB*NE_*HH, 256>>>(att, mpos);

    // hsW / tsW : [168,768] = E @ W1
    k_hgemm<<<dim3(6,3,1), 256>>>(p_eHi, p_eLo, 0, p_W1hF, 0,
                                  p_hsW, nullptr, nullptr, BB*NE_, 48,
                                  nullptr, nullptr, nullptr, 0);
    k_hgemm<<<dim3(6,3,1), 256>>>(p_eHi, p_eLo, 0, p_W1tF, 0,
                                  p_tsW, nullptr, nullptr, BB*NE_, 48,
                                  nullptr, nullptr, nullptr, 0);

    k_pairw<<<BB*PP, 256>>>(hts);

    // rs : per-doc [512,1024]@[1024,768] -> split pairs
    k_hgemm<<<dim3(6,8,BB), 256>>>(p_wnHi, p_wnLo, (long)PP*(LLEN/2),
                                   p_seqF, (long)96*64*32,
                                   nullptr, p_rsHi, p_rsLo, PP, 64,
                                   nullptr, nullptr, nullptr, 0);

    // zs / zo : [2048,768]@[768,768] + gather + bias + tanh
    k_hgemm<<<dim3(6,32,1), 256>>>(p_rsHi, p_rsLo, 0, p_W2hF, 0,
                                   p_zs, nullptr, nullptr, BB*PP, 48,
                                   bh, p_hsW, hts, 0);
    k_hgemm<<<dim3(6,32,1), 256>>>(p_rsHi, p_rsLo, 0, p_W2tF, 0,
                                   p_zo, nullptr, nullptr, BB*PP, 48,
                                   bt, p_tsW, hts, 1);

    k_bilinear<<<dim3(32, NG_), 256>>>();
    k_finish<<<(BB*PP*NL_ + 255)/256, 256>>>(out, bbi);
}

// round 14
// speedup vs baseline: 1.3428x; 1.3428x over previous
#include <cuda_runtime.h>
#include <cuda_bf16.h>
#include <cstdint>
#include <math.h>

#define BB   4
#define LLEN 1024
#define DD   768
#define HH   12
#define NE_  42
#define MM   4
#define PP   512
#define NL_  97
#define NG_  12      // D / BLK
#define NT_  13      // bilinear n-tiles of 8 (97 -> 104)

// ---------------- scratch (static device globals; no runtime allocation) ----
__device__ float g_ent_att[BB*NE_*HH*LLEN];
__device__ float g_hsW[BB*NE_*DD];
__device__ float g_tsW[BB*NE_*DD];
__device__ float g_zs[BB*PP*DD];
__device__ float g_zo[BB*PP*DD];
__device__ float g_part[NG_][BB*PP*NL_];
// pair-split bf16 operands (u32 = 2 adjacent-k bf16)
__device__ uint32_t g_eHi[BB*NE_*DD/2],  g_eLo[BB*NE_*DD/2];
__device__ uint32_t g_wnHi[BB*PP*LLEN/2], g_wnLo[BB*PP*LLEN/2];
__device__ uint32_t g_rsHi[BB*PP*DD/2],  g_rsLo[BB*PP*DD/2];
// B fragment arrays: [t][s][lane] uint4 {bhi0,bhi1,blo0,blo1}
__device__ uint4 g_seqF[(size_t)BB*96*64*32];
__device__ uint4 g_W1hF[96*48*32], g_W1tF[96*48*32];
__device__ uint4 g_W2hF[96*48*32], g_W2tF[96*48*32];
// bilinear W fragments: [g][s][t][lane]
__device__ uint4 g_Wfrag[(size_t)NG_*256*NT_*32];

// ---------------- helpers ---------------------------------------------------
__device__ __forceinline__ void cpa16(void* dst, const void* src){
    unsigned d = (unsigned)__cvta_generic_to_shared(dst);
    asm volatile("cp.async.cg.shared.global [%0], [%1], 16;\n" :: "r"(d), "l"(src));
}
__device__ __forceinline__ void cpa_commit(){ asm volatile("cp.async.commit_group;\n"); }
__device__ __forceinline__ void cpa_wait1(){ asm volatile("cp.async.wait_group 1;\n"); }
__device__ __forceinline__ void cpa_wait0(){ asm volatile("cp.async.wait_group 0;\n"); }

__device__ __forceinline__ uint32_t pack_split(float a, float b, uint32_t& lo){
    __nv_bfloat16 ha = __float2bfloat16(a), hb = __float2bfloat16(b);
    float ra = a - __bfloat162float(ha);
    float rb = b - __bfloat162float(hb);
    __nv_bfloat16 la = __float2bfloat16(ra), lb = __float2bfloat16(rb);
    lo = (uint32_t)__bfloat16_as_ushort(la) | ((uint32_t)__bfloat16_as_ushort(lb) << 16);
    return (uint32_t)__bfloat16_as_ushort(ha) | ((uint32_t)__bfloat16_as_ushort(hb) << 16);
}
__device__ __forceinline__ void mma16816(float* d,
    uint32_t a0, uint32_t a1, uint32_t a2, uint32_t a3,
    uint32_t b0, uint32_t b1){
    asm volatile("mma.sync.aligned.m16n8k16.row.col.f32.bf16.bf16.f32 "
        "{%0,%1,%2,%3}, {%4,%5,%6,%7}, {%8,%9}, {%0,%1,%2,%3};\n"
        : "+f"(d[0]), "+f"(d[1]), "+f"(d[2]), "+f"(d[3])
        : "r"(a0), "r"(a1), "r"(a2), "r"(a3), "r"(b0), "r"(b1));
}

// ---------------- kernel 1: entity embeddings -> split pairs ----------------
__global__ void k_ent_emb(const float* __restrict__ seq, const int* __restrict__ mpos){
    int be = blockIdx.x;
    int b  = be / NE_;
    const int* mp = mpos + be*MM;
    int p0 = mp[0]+1, p1 = mp[1]+1, p2 = mp[2]+1, p3 = mp[3]+1;
    const float* s = seq + (size_t)b*LLEN*DD;
    for (int d2 = threadIdx.x; d2 < DD/2; d2 += blockDim.x){
        float v[2];
        #pragma unroll
        for (int e = 0; e < 2; ++e){
            int d = 2*d2 + e;
            float v0 = s[(size_t)p0*DD+d], v1 = s[(size_t)p1*DD+d];
            float v2 = s[(size_t)p2*DD+d], v3 = s[(size_t)p3*DD+d];
            float mx = fmaxf(fmaxf(v0,v1), fmaxf(v2,v3));
            float sm = expf(v0-mx)+expf(v1-mx)+expf(v2-mx)+expf(v3-mx);
            v[e] = mx + logf(sm);
        }
        uint32_t lo; uint32_t hi = pack_split(v[0], v[1], lo);
        g_eHi[(size_t)be*(DD/2) + d2] = hi;
        g_eLo[(size_t)be*(DD/2) + d2] = lo;
    }
}

// ---------------- kernel 2: entity attention rows ---------------------------
__global__ void k_ent_att(const float* __restrict__ att, const int* __restrict__ mpos){
    int beh = blockIdx.x;
    int h   = beh % HH;
    int be  = beh / HH;
    int b   = be / NE_;
    const int* mp = mpos + be*MM;
    int p0 = mp[0]+1, p1 = mp[1]+1, p2 = mp[2]+1, p3 = mp[3]+1;
    const float* A = att + ((size_t)(b*HH + h))*LLEN*LLEN;
    float* out = g_ent_att + ((size_t)be*HH + h)*LLEN;
    for (int l = threadIdx.x; l < LLEN; l += blockDim.x){
        float v = A[(size_t)p0*LLEN+l] + A[(size_t)p1*LLEN+l]
                + A[(size_t)p2*LLEN+l] + A[(size_t)p3*LLEN+l];
        out[l] = v * 0.25f;
    }
}

// ---------------- kernel 3: pair weights -> split pairs ---------------------
__global__ void k_pairw(const int* __restrict__ hts){
    int bp = blockIdx.x;
    int b  = bp >> 9;
    int hi_ = hts[bp*2+0], ti = hts[bp*2+1];
    __shared__ float sd[LLEN];
    __shared__ float red[8];
    const float* Ah = g_ent_att + ((size_t)(b*NE_ + hi_))*HH*LLEN;
    const float* At = g_ent_att + ((size_t)(b*NE_ + ti))*HH*LLEN;
    float lsum = 0.f;
    for (int l = threadIdx.x; l < LLEN; l += blockDim.x){
        float s = 0.f;
        #pragma unroll
        for (int h = 0; h < HH; ++h) s += Ah[h*LLEN+l]*At[h*LLEN+l];
        sd[l] = s; lsum += s;
    }
    #pragma unroll
    for (int o = 16; o; o >>= 1) lsum += __shfl_xor_sync(0xFFFFFFFFu, lsum, o);
    if ((threadIdx.x & 31) == 0) red[threadIdx.x >> 5] = lsum;
    __syncthreads();
    float total = red[0]+red[1]+red[2]+red[3]+red[4]+red[5]+red[6]+red[7];
    float inv = 1.f / (total + (float)HH*1e-5f);
    for (int l2 = threadIdx.x; l2 < LLEN/2; l2 += blockDim.x){
        uint32_t lo; uint32_t hi = pack_split(sd[2*l2]*inv, sd[2*l2+1]*inv, lo);
        g_wnHi[(size_t)bp*(LLEN/2) + l2] = hi;
        g_wnLo[(size_t)bp*(LLEN/2) + l2] = lo;
    }
}

// ---------------- pack B operand [16s x 768n] fp32 -> mma fragments ---------
__global__ void __launch_bounds__(128) k_packB(const float* __restrict__ src, long sSrc,
                                               uint4* __restrict__ dst, long sDst, int S){
    __shared__ float w_sh[16*768];
    int tid = threadIdx.x;
    int s = blockIdx.x;
    const float* s0 = src + (size_t)blockIdx.y*sSrc + (size_t)s*16*768;
    for (int idx = tid; idx < 16*768; idx += 128) w_sh[idx] = s0[idx];
    __syncthreads();
    uint4* d0 = dst + (size_t)blockIdx.y*sDst;
    for (int e = tid; e < 96*32; e += 128){
        int t = e >> 5, lane = e & 31;
        int gid = lane >> 2, q = lane & 3;
        int n = t*8 + gid, k0 = q*2;
        uint32_t l0, l1; uint4 F;
        F.x = pack_split(w_sh[k0*768+n],     w_sh[(k0+1)*768+n], l0);
        F.y = pack_split(w_sh[(k0+8)*768+n], w_sh[(k0+9)*768+n], l1);
        F.z = l0; F.w = l1;
        d0[((size_t)t*S + s)*32 + lane] = F;
    }
}

// ---------------- HMMA bf16x3 GEMM, SMEM-staged B + prefetched A ------------
// CTA 128m x 64n, 8 warps = 8 m16 subtiles; warp covers n64 (8 tiles).
__global__ void __launch_bounds__(256,2) k_hgemm2(
    const uint32_t* __restrict__ Ahi, const uint32_t* __restrict__ Alo, long sA,
    const uint4* __restrict__ Bf0, const uint4* __restrict__ Bf1, long sB,
    float* __restrict__ Cout0, float* __restrict__ Cout1,
    uint32_t* __restrict__ CpHi, uint32_t* __restrict__ CpLo,
    int Mr, int S, int wset,
    const float* __restrict__ bias0, const float* __restrict__ bias1,
    const float* __restrict__ eW0, const float* __restrict__ eW1,
    const int* __restrict__ hts)
{
    __shared__ __align__(16) uint4 Bs[2][8][32];      // 8 KB
    int tid = threadIdx.x, lane = tid & 31, wid = tid >> 5;
    int gid = lane >> 2, q = lane & 3;
    int z = blockIdx.z;
    int Kd2 = S*8;

    const uint32_t* AH = Ahi + (wset ? 0 : (size_t)z*sA);
    const uint32_t* AL = Alo + (wset ? 0 : (size_t)z*sA);
    const uint4* BF = (wset && z == 1) ? Bf1 : Bf0;
    if (!wset) BF += (size_t)z*sB;

    int nt0 = blockIdx.x*8;
    int row0 = blockIdx.y*128 + wid*16 + gid;
    int row8 = row0 + 8;
    int rc0 = min(row0, Mr-1), rc8 = min(row8, Mr-1);
    const uint32_t* ah0 = AH + (size_t)rc0*Kd2;
    const uint32_t* ah8 = AH + (size_t)rc8*Kd2;
    const uint32_t* al0 = AL + (size_t)rc0*Kd2;
    const uint32_t* al8 = AL + (size_t)rc8*Kd2;

    // this thread's staging source: tile tt=tid>>5
    const uint4* bsrc = BF + ((size_t)(nt0 + (tid>>5))*S)*32 + lane;
    uint4* bdst0 = &Bs[0][tid>>5][lane];
    uint4* bdst1 = &Bs[1][tid>>5][lane];

    float acc[8][4];
    #pragma unroll
    for (int tt = 0; tt < 8; ++tt){
        acc[tt][0]=0.f; acc[tt][1]=0.f; acc[tt][2]=0.f; acc[tt][3]=0.f;
    }

    // prologue: stage s=0, load A(0)
    cpa16(bdst0, bsrc); cpa_commit();
    uint32_t cAh0 = ah0[q],   cAh1 = ah8[q],   cAh2 = ah0[4+q],   cAh3 = ah8[4+q];
    uint32_t cAl0 = al0[q],   cAl1 = al8[q],   cAl2 = al0[4+q],   cAl3 = al8[4+q];

    for (int s = 0; s < S; ++s){
        int b = s & 1;
        if (s+1 < S){
            cpa16(b ? bdst0 : bdst1, bsrc + (size_t)(s+1)*32);
            cpa_commit();
            cpa_wait1();
        } else {
            cpa_wait0();
        }
        __syncthreads();
        // prefetch A(s+1)
        int sn = (s+1 < S) ? s+1 : s;
        int i0 = sn*8 + q, i1 = sn*8 + 4 + q;
        uint32_t nAh0 = ah0[i0], nAh1 = ah8[i0], nAh2 = ah0[i1], nAh3 = ah8[i1];
        uint32_t nAl0 = al0[i0], nAl1 = al8[i0], nAl2 = al0[i1], nAl3 = al8[i1];
        #pragma unroll
        for (int tt = 0; tt < 8; ++tt){
            uint4 B = Bs[b][tt][lane];
            mma16816(acc[tt], cAh0,cAh1,cAh2,cAh3, B.x, B.y);   // hi*hi
            mma16816(acc[tt], cAh0,cAh1,cAh2,cAh3, B.z, B.w);   // hi*lo
            mma16816(acc[tt], cAl0,cAl1,cAl2,cAl3, B.x, B.y);   // lo*hi
        }
        __syncthreads();
        cAh0=nAh0; cAh1=nAh1; cAh2=nAh2; cAh3=nAh3;
        cAl0=nAl0; cAl1=nAl1; cAl2=nAl2; cAl3=nAl3;
    }

    // ---- epilogue ----
    bool sel1 = (wset && z == 1);
    float* Cout = sel1 ? Cout1 : Cout0;
    const float* bias = sel1 ? bias1 : bias0;
    const float* eW   = sel1 ? eW1   : eW0;
    const float* eWu  = eW ? eW : eW0;
    int which = wset ? z : 0;
    int crow0 = wset ? row0 : z*Mr + row0;
    int crow8 = wset ? row8 : z*Mr + row8;
    bool hasEpi = (eW0 != nullptr) || (eW1 != nullptr);
    const float *ev0 = 0, *ev8 = 0;
    if (hasEpi){
        ev0 = eWu + ((size_t)((crow0 >> 9)*NE_ + hts[crow0*2 + which]))*DD;
        ev8 = eWu + ((size_t)((crow8 >> 9)*NE_ + hts[crow8*2 + which]))*DD;
    }
    int nbase = nt0*8;
    #pragma unroll
    for (int tt = 0; tt < 8; ++tt){
        int n0 = nbase + tt*8 + q*2;
        float v0 = acc[tt][0], v1 = acc[tt][1], v2 = acc[tt][2], v3 = acc[tt][3];
        if (hasEpi){
            v0 = tanhf(v0 + ev0[n0]   + bias[n0]);
            v1 = tanhf(v1 + ev0[n0+1] + bias[n0+1]);
            v2 = tanhf(v2 + ev8[n0]   + bias[n0]);
            v3 = tanhf(v3 + ev8[n0+1] + bias[n0+1]);
        }
        if (Cout){
            if (row0 < Mr) *(float2*)&Cout[(size_t)crow0*DD + n0] = make_float2(v0, v1);
            if (row8 < Mr) *(float2*)&Cout[(size_t)crow8*DD + n0] = make_float2(v2, v3);
        } else {
            uint32_t lo0, lo8;
            uint32_t hi0 = pack_split(v0, v1, lo0);
            uint32_t hi8 = pack_split(v2, v3, lo8);
            if (row0 < Mr){
                CpHi[(size_t)crow0*(DD/2) + (n0>>1)] = hi0;
                CpLo[(size_t)crow0*(DD/2) + (n0>>1)] = lo0;
            }
            if (row8 < Mr){
                CpHi[(size_t)crow8*(DD/2) + (n0>>1)] = hi8;
                CpLo[(size_t)crow8*(DD/2) + (n0>>1)] = lo8;
            }
        }
    }
}

// ---------------- prep: W_bi -> per-thread mma B fragments ------------------
__global__ void __launch_bounds__(128) k_prepW(const float* __restrict__ Wbi){
    int bid = blockIdx.x;
    int g = bid >> 8, s = bid & 255;
    __shared__ float w_sh[16][104];
    int tid = threadIdx.x;
    for (int idx = tid; idx < 16*104; idx += 128){
        int r = idx / 104, n = idx - r*104;
        w_sh[r][n] = (n < NL_) ? Wbi[(size_t)(g*4096 + s*16 + r)*NL_ + n] : 0.f;
    }
    __syncthreads();
    for (int e = tid; e < NT_*32; e += 128){
        int t = e >> 5, lane = e & 31;
        int gid = lane >> 2, q = lane & 3;
        int n = t*8 + gid;
        int k0 = q*2;
        float w0 = w_sh[k0][n],   w1 = w_sh[k0+1][n];
        float w2 = w_sh[k0+8][n], w3 = w_sh[k0+9][n];
        uint4 F; uint32_t l0, l1;
        F.x = pack_split(w0, w1, l0);
        F.y = pack_split(w2, w3, l1);
        F.z = l0; F.w = l1;
        g_Wfrag[(((size_t)g*256 + s)*NT_ + t)*32 + lane] = F;
    }
}

// ---------------- HMMA bf16-split grouped bilinear (R7, proven) -------------
__global__ void __launch_bounds__(256,2) k_bilinear(){
    __shared__ float zs_sh[64*65];
    __shared__ float zo_sh[64*65];
    int tid = threadIdx.x, lane = tid & 31, wid = tid >> 5;
    int pb = wid >> 1, nh = wid & 1;
    int g  = blockIdx.y;
    int p0 = blockIdx.x * 64;

    for (int idx = tid; idx < 64*16; idx += 256){
        int p = idx >> 4, c4 = idx & 15;
        float4 vs = *(const float4*)(g_zs + (size_t)(p0+p)*DD + g*64 + c4*4);
        float4 vo = *(const float4*)(g_zo + (size_t)(p0+p)*DD + g*64 + c4*4);
        zs_sh[p*65 + c4*4+0] = vs.x; zs_sh[p*65 + c4*4+1] = vs.y;
        zs_sh[p*65 + c4*4+2] = vs.z; zs_sh[p*65 + c4*4+3] = vs.w;
        zo_sh[p*65 + c4*4+0] = vo.x; zo_sh[p*65 + c4*4+1] = vo.y;
        zo_sh[p*65 + c4*4+2] = vo.z; zo_sh[p*65 + c4*4+3] = vo.w;
    }
    __syncthreads();

    int gid = lane >> 2, q = lane & 3;
    int r0 = pb*16 + gid, r8 = r0 + 8;
    int t0 = nh * 6;
    const uint4* bbase = g_Wfrag + (((size_t)g*256)*NT_ + t0)*32 + lane;

    float acc[7][4];
    #pragma unroll
    for (int tt = 0; tt < 7; ++tt){
        acc[tt][0] = 0.f; acc[tt][1] = 0.f; acc[tt][2] = 0.f; acc[tt][3] = 0.f;
    }

    for (int s = 0; s < 256; ++s){
        uint4 Bf[7];
        const uint4* bp = bbase + (size_t)s*(NT_*32);
        #pragma unroll
        for (int tt = 0; tt < 7; ++tt) Bf[tt] = bp[tt*32];

        int i  = s >> 2;
        int c0 = ((s & 3) << 4) + q*2;
        float zr0 = zs_sh[r0*65 + i], zr8 = zs_sh[r8*65 + i];
        float o00 = zo_sh[r0*65 + c0],   o01 = zo_sh[r0*65 + c0+1];
        float o08 = zo_sh[r0*65 + c0+8], o09 = zo_sh[r0*65 + c0+9];
        float o80 = zo_sh[r8*65 + c0],   o81 = zo_sh[r8*65 + c0+1];
        float o88 = zo_sh[r8*65 + c0+8], o89 = zo_sh[r8*65 + c0+9];
        uint32_t al0, al1, al2, al3;
        uint32_t ah0 = pack_split(zr0*o00, zr0*o01, al0);
        uint32_t ah1 = pack_split(zr8*o80, zr8*o81, al1);
        uint32_t ah2 = pack_split(zr0*o08, zr0*o09, al2);
        uint32_t ah3 = pack_split(zr8*o88, zr8*o89, al3);

        #pragma unroll
        for (int tt = 0; tt < 7; ++tt){
            mma16816(acc[tt], ah0, ah1, ah2, ah3, Bf[tt].x, Bf[tt].y);
            mma16816(acc[tt], ah0, ah1, ah2, ah3, Bf[tt].z, Bf[tt].w);
            mma16816(acc[tt], al0, al1, al2, al3, Bf[tt].x, Bf[tt].y);
        }
    }

    int row0g = p0 + r0, row8g = p0 + r8;
    #pragma unroll
    for (int tt = 0; tt < 7; ++tt){
        int n0 = (t0 + tt)*8 + q*2;
        if (n0 < NL_){
            g_part[g][(size_t)row0g*NL_ + n0] = acc[tt][0];
            g_part[g][(size_t)row8g*NL_ + n0] = acc[tt][2];
        }
        if (n0 + 1 < NL_){
            g_part[g][(size_t)row0g*NL_ + n0+1] = acc[tt][1];
            g_part[g][(size_t)row8g*NL_ + n0+1] = acc[tt][3];
        }
    }
}

// ---------------- finish: sum 12 partials + bias ----------------------------
__global__ void k_finish(float* __restrict__ out, const float* __restrict__ b_bi){
    int i = blockIdx.x*blockDim.x + threadIdx.x;
    if (i < BB*PP*NL_){
        float s = b_bi[i % NL_];
        #pragma unroll
        for (int q = 0; q < NG_; ++q) s += g_part[q][i];
        out[i] = s;
    }
}

// ---------------- launch ----------------------------------------------------
extern "C" void kernel_launch(void* const* d_in, const int* in_sizes, int n_in,
                              void* d_out, int out_size){
    const float* seq  = (const float*)d_in[0];
    const float* att  = (const float*)d_in[1];
    const int*   mpos = (const int*)  d_in[2];
    const int*   hts  = (const int*)  d_in[3];
    const float* Wh   = (const float*)d_in[4];
    const float* bh   = (const float*)d_in[5];
    const float* Wt   = (const float*)d_in[6];
    const float* bt   = (const float*)d_in[7];
    const float* Wbi  = (const float*)d_in[8];
    const float* bbi  = (const float*)d_in[9];
    float* out = (float*)d_out;

    float *p_hsW, *p_tsW, *p_zs, *p_zo;
    uint32_t *p_eHi, *p_eLo, *p_wnHi, *p_wnLo, *p_rsHi, *p_rsLo;
    uint4 *p_seqF, *p_W1hF, *p_W1tF, *p_W2hF, *p_W2tF;
    cudaGetSymbolAddress((void**)&p_hsW,  g_hsW);
    cudaGetSymbolAddress((void**)&p_tsW,  g_tsW);
    cudaGetSymbolAddress((void**)&p_zs,   g_zs);
    cudaGetSymbolAddress((void**)&p_zo,   g_zo);
    cudaGetSymbolAddress((void**)&p_eHi,  g_eHi);
    cudaGetSymbolAddress((void**)&p_eLo,  g_eLo);
    cudaGetSymbolAddress((void**)&p_wnHi, g_wnHi);
    cudaGetSymbolAddress((void**)&p_wnLo, g_wnLo);
    cudaGetSymbolAddress((void**)&p_rsHi, g_rsHi);
    cudaGetSymbolAddress((void**)&p_rsLo, g_rsLo);
    cudaGetSymbolAddress((void**)&p_seqF, g_seqF);
    cudaGetSymbolAddress((void**)&p_W1hF, g_W1hF);
    cudaGetSymbolAddress((void**)&p_W1tF, g_W1tF);
    cudaGetSymbolAddress((void**)&p_W2hF, g_W2hF);
    cudaGetSymbolAddress((void**)&p_W2tF, g_W2tF);

    // operand prep
    k_prepW<<<NG_*256, 128>>>(Wbi);
    k_packB<<<dim3(64, BB), 128>>>(seq, (long)LLEN*DD, p_seqF, (long)96*64*32, 64);
    k_packB<<<dim3(48, 1), 128>>>(Wh,                 0, p_W1hF, 0, 48);
    k_packB<<<dim3(48, 1), 128>>>(Wt,                 0, p_W1tF, 0, 48);
    k_packB<<<dim3(48, 1), 128>>>(Wh + (size_t)DD*DD, 0, p_W2hF, 0, 48);
    k_packB<<<dim3(48, 1), 128>>>(Wt + (size_t)DD*DD, 0, p_W2tF, 0, 48);

    k_ent_emb<<<BB*NE_, 256>>>(seq, mpos);
    k_ent_att<<<BB*NE_*HH, 256>>>(att, mpos);

    // hsW / tsW : [168,768] = E @ W1{h,t}  (fused via z)
    k_hgemm2<<<dim3(12, 2, 2), 256>>>(p_eHi, p_eLo, 0,
                                      p_W1hF, p_W1tF, 0,
                                      p_hsW, p_tsW, nullptr, nullptr,
                                      BB*NE_, 48, 1,
                                      nullptr, nullptr, nullptr, nullptr, nullptr);

    k_pairw<<<BB*PP, 256>>>(hts);

    // rs : per-doc [512,1024]@[1024,768] -> split pairs (z = batch)
    k_hgemm2<<<dim3(12, 4, BB), 256>>>(p_wnHi, p_wnLo, (long)PP*(LLEN/2),
                                       p_seqF, nullptr, (long)96*64*32,
                                       nullptr, nullptr, p_rsHi, p_rsLo,
                                       PP, 64, 0,
                                       nullptr, nullptr, nullptr, nullptr, nullptr);

    // zs / zo : [2048,768]@[768,768] + gather + bias + tanh (fused via z)
    k_hgemm2<<<dim3(12, 16, 2), 256>>>(p_rsHi, p_rsLo, 0,
                                       p_W2hF, p_W2tF, 0,
                                       p_zs, p_zo, nullptr, nullptr,
                                       BB*PP, 48, 1,
                                       bh, bt, p_hsW, p_tsW, hts);

    k_bilinear<<<dim3(32, NG_), 256>>>();
    k_finish<<<(BB*PP*NL_ + 255)/256, 256>>>(out, bbi);
}

// round 15
// speedup vs baseline: 1.8583x; 1.3839x over previous
#include <cuda_runtime.h>
#include <cuda_bf16.h>
#include <cstdint>
#include <math.h>

#define BB   4
#define LLEN 1024
#define DD   768
#define HH   12
#define NE_  42
#define MM   4
#define PP   512
#define NL_  97
#define NG_  12      // D / BLK
#define NT_  13      // bilinear n-tiles of 8 (97 -> 104)

// ---------------- scratch (static device globals; no runtime allocation) ----
__device__ float g_ent_att[BB*NE_*HH*LLEN];
__device__ float g_hsW[BB*NE_*DD];
__device__ float g_tsW[BB*NE_*DD];
__device__ float g_zs[BB*PP*DD];
__device__ float g_zo[BB*PP*DD];
__device__ float g_part[NG_][BB*PP*NL_];
// pair-split bf16 operands (u32 = 2 adjacent-k bf16)
__device__ uint32_t g_eHi[BB*NE_*DD/2],  g_eLo[BB*NE_*DD/2];
__device__ uint32_t g_wnHi[BB*PP*LLEN/2], g_wnLo[BB*PP*LLEN/2];
__device__ uint32_t g_rsHi[BB*PP*DD/2],  g_rsLo[BB*PP*DD/2];
// B fragment arrays: [t][s][lane] uint4 {bhi0,bhi1,blo0,blo1}
__device__ uint4 g_seqF[(size_t)BB*96*64*32];
__device__ uint4 g_W1hF[96*48*32], g_W1tF[96*48*32];
__device__ uint4 g_W2hF[96*48*32], g_W2tF[96*48*32];
// bilinear W fragments: [g][s][t][lane]
__device__ uint4 g_Wfrag[(size_t)NG_*256*NT_*32];

// ---------------- helpers ---------------------------------------------------
__device__ __forceinline__ void cpa16(void* dst, const void* src){
    unsigned d = (unsigned)__cvta_generic_to_shared(dst);
    asm volatile("cp.async.cg.shared.global [%0], [%1], 16;\n" :: "r"(d), "l"(src));
}
__device__ __forceinline__ void cpa_commit(){ asm volatile("cp.async.commit_group;\n"); }
__device__ __forceinline__ void cpa_wait1(){ asm volatile("cp.async.wait_group 1;\n"); }
__device__ __forceinline__ void cpa_wait0(){ asm volatile("cp.async.wait_group 0;\n"); }

__device__ __forceinline__ uint32_t pack_split(float a, float b, uint32_t& lo){
    __nv_bfloat16 ha = __float2bfloat16(a), hb = __float2bfloat16(b);
    float ra = a - __bfloat162float(ha);
    float rb = b - __bfloat162float(hb);
    __nv_bfloat16 la = __float2bfloat16(ra), lb = __float2bfloat16(rb);
    lo = (uint32_t)__bfloat16_as_ushort(la) | ((uint32_t)__bfloat16_as_ushort(lb) << 16);
    return (uint32_t)__bfloat16_as_ushort(ha) | ((uint32_t)__bfloat16_as_ushort(hb) << 16);
}
__device__ __forceinline__ void mma16816(float* d,
    uint32_t a0, uint32_t a1, uint32_t a2, uint32_t a3,
    uint32_t b0, uint32_t b1){
    asm volatile("mma.sync.aligned.m16n8k16.row.col.f32.bf16.bf16.f32 "
        "{%0,%1,%2,%3}, {%4,%5,%6,%7}, {%8,%9}, {%0,%1,%2,%3};\n"
        : "+f"(d[0]), "+f"(d[1]), "+f"(d[2]), "+f"(d[3])
        : "r"(a0), "r"(a1), "r"(a2), "r"(a3), "r"(b0), "r"(b1));
}

// ---------------- kernel 1: entity embeddings -> split pairs ----------------
__global__ void k_ent_emb(const float* __restrict__ seq, const int* __restrict__ mpos){
    int be = blockIdx.x;
    int b  = be / NE_;
    const int* mp = mpos + be*MM;
    int p0 = mp[0]+1, p1 = mp[1]+1, p2 = mp[2]+1, p3 = mp[3]+1;
    const float* s = seq + (size_t)b*LLEN*DD;
    for (int d2 = threadIdx.x; d2 < DD/2; d2 += blockDim.x){
        float v[2];
        #pragma unroll
        for (int e = 0; e < 2; ++e){
            int d = 2*d2 + e;
            float v0 = s[(size_t)p0*DD+d], v1 = s[(size_t)p1*DD+d];
            float v2 = s[(size_t)p2*DD+d], v3 = s[(size_t)p3*DD+d];
            float mx = fmaxf(fmaxf(v0,v1), fmaxf(v2,v3));
            float sm = expf(v0-mx)+expf(v1-mx)+expf(v2-mx)+expf(v3-mx);
            v[e] = mx + logf(sm);
        }
        uint32_t lo; uint32_t hi = pack_split(v[0], v[1], lo);
        g_eHi[(size_t)be*(DD/2) + d2] = hi;
        g_eLo[(size_t)be*(DD/2) + d2] = lo;
    }
}

// ---------------- kernel 2: entity attention rows ---------------------------
__global__ void k_ent_att(const float* __restrict__ att, const int* __restrict__ mpos){
    int beh = blockIdx.x;
    int h   = beh % HH;
    int be  = beh / HH;
    int b   = be / NE_;
    const int* mp = mpos + be*MM;
    int p0 = mp[0]+1, p1 = mp[1]+1, p2 = mp[2]+1, p3 = mp[3]+1;
    const float* A = att + ((size_t)(b*HH + h))*LLEN*LLEN;
    float* out = g_ent_att + ((size_t)be*HH + h)*LLEN;
    for (int l = threadIdx.x; l < LLEN; l += blockDim.x){
        float v = A[(size_t)p0*LLEN+l] + A[(size_t)p1*LLEN+l]
                + A[(size_t)p2*LLEN+l] + A[(size_t)p3*LLEN+l];
        out[l] = v * 0.25f;
    }
}

// ---------------- kernel 3: pair weights -> split pairs ---------------------
__global__ void k_pairw(const int* __restrict__ hts){
    int bp = blockIdx.x;
    int b  = bp >> 9;
    int hi_ = hts[bp*2+0], ti = hts[bp*2+1];
    __shared__ float sd[LLEN];
    __shared__ float red[8];
    const float* Ah = g_ent_att + ((size_t)(b*NE_ + hi_))*HH*LLEN;
    const float* At = g_ent_att + ((size_t)(b*NE_ + ti))*HH*LLEN;
    float lsum = 0.f;
    for (int l = threadIdx.x; l < LLEN; l += blockDim.x){
        float s = 0.f;
        #pragma unroll
        for (int h = 0; h < HH; ++h) s += Ah[h*LLEN+l]*At[h*LLEN+l];
        sd[l] = s; lsum += s;
    }
    #pragma unroll
    for (int o = 16; o; o >>= 1) lsum += __shfl_xor_sync(0xFFFFFFFFu, lsum, o);
    if ((threadIdx.x & 31) == 0) red[threadIdx.x >> 5] = lsum;
    __syncthreads();
    float total = red[0]+red[1]+red[2]+red[3]+red[4]+red[5]+red[6]+red[7];
    float inv = 1.f / (total + (float)HH*1e-5f);
    for (int l2 = threadIdx.x; l2 < LLEN/2; l2 += blockDim.x){
        uint32_t lo; uint32_t hi = pack_split(sd[2*l2]*inv, sd[2*l2+1]*inv, lo);
        g_wnHi[(size_t)bp*(LLEN/2) + l2] = hi;
        g_wnLo[(size_t)bp*(LLEN/2) + l2] = lo;
    }
}

// ---------------- pack B operand [16s x 768n] fp32 -> mma fragments ---------
__device__ __forceinline__ void packB_body(const float* __restrict__ s0,
                                           uint4* __restrict__ d0, int s, int S){
    __shared__ float w_sh[16*768];
    int tid = threadIdx.x;
    const float4* s4 = (const float4*)s0;
    for (int idx = tid; idx < 16*768/4; idx += 256)
        ((float4*)w_sh)[idx] = s4[idx];
    __syncthreads();
    for (int e = tid; e < 96*32; e += 256){
        int t = e >> 5, lane = e & 31;
        int gid = lane >> 2, q = lane & 3;
        int n = t*8 + gid, k0 = q*2;
        uint32_t l0, l1; uint4 F;
        F.x = pack_split(w_sh[k0*768+n],     w_sh[(k0+1)*768+n], l0);
        F.y = pack_split(w_sh[(k0+8)*768+n], w_sh[(k0+9)*768+n], l1);
        F.z = l0; F.w = l1;
        d0[((size_t)t*S + s)*32 + lane] = F;
    }
}

__global__ void __launch_bounds__(256) k_packB(const float* __restrict__ src, long sSrc,
                                               uint4* __restrict__ dst, long sDst, int S){
    packB_body(src + (size_t)blockIdx.y*sSrc + (size_t)blockIdx.x*16*768,
               dst + (size_t)blockIdx.y*sDst, blockIdx.x, S);
}

// all four extractor weight packs in one launch (grid 48 x 4)
__global__ void __launch_bounds__(256) k_packW(const float* __restrict__ Wh,
                                               const float* __restrict__ Wt,
                                               uint4* d1h, uint4* d1t,
                                               uint4* d2h, uint4* d2t){
    int w = blockIdx.y;
    const float* src = (w==0) ? Wh : (w==1) ? Wt
                     : (w==2) ? Wh + (size_t)DD*DD : Wt + (size_t)DD*DD;
    uint4* dst = (w==0) ? d1h : (w==1) ? d1t : (w==2) ? d2h : d2t;
    packB_body(src + (size_t)blockIdx.x*16*768, dst, blockIdx.x, 48);
}

// ---------------- HMMA bf16x3 GEMM, SMEM-staged B + prefetched A ------------
__global__ void __launch_bounds__(256,2) k_hgemm2(
    const uint32_t* __restrict__ Ahi, const uint32_t* __restrict__ Alo, long sA,
    const uint4* __restrict__ Bf0, const uint4* __restrict__ Bf1, long sB,
    float* __restrict__ Cout0, float* __restrict__ Cout1,
    uint32_t* __restrict__ CpHi, uint32_t* __restrict__ CpLo,
    int Mr, int S, int wset,
    const float* __restrict__ bias0, const float* __restrict__ bias1,
    const float* __restrict__ eW0, const float* __restrict__ eW1,
    const int* __restrict__ hts)
{
    __shared__ __align__(16) uint4 Bs[2][8][32];
    int tid = threadIdx.x, lane = tid & 31, wid = tid >> 5;
    int gid = lane >> 2, q = lane & 3;
    int z = blockIdx.z;
    int Kd2 = S*8;

    const uint32_t* AH = Ahi + (wset ? 0 : (size_t)z*sA);
    const uint32_t* AL = Alo + (wset ? 0 : (size_t)z*sA);
    const uint4* BF = (wset && z == 1) ? Bf1 : Bf0;
    if (!wset) BF += (size_t)z*sB;

    int nt0 = blockIdx.x*8;
    int row0 = blockIdx.y*128 + wid*16 + gid;
    int row8 = row0 + 8;
    int rc0 = min(row0, Mr-1), rc8 = min(row8, Mr-1);
    const uint32_t* ah0 = AH + (size_t)rc0*Kd2;
    const uint32_t* ah8 = AH + (size_t)rc8*Kd2;
    const uint32_t* al0 = AL + (size_t)rc0*Kd2;
    const uint32_t* al8 = AL + (size_t)rc8*Kd2;

    const uint4* bsrc = BF + ((size_t)(nt0 + (tid>>5))*S)*32 + lane;
    uint4* bdst0 = &Bs[0][tid>>5][lane];
    uint4* bdst1 = &Bs[1][tid>>5][lane];

    float acc[8][4];
    #pragma unroll
    for (int tt = 0; tt < 8; ++tt){
        acc[tt][0]=0.f; acc[tt][1]=0.f; acc[tt][2]=0.f; acc[tt][3]=0.f;
    }

    cpa16(bdst0, bsrc); cpa_commit();
    uint32_t cAh0 = ah0[q],   cAh1 = ah8[q],   cAh2 = ah0[4+q],   cAh3 = ah8[4+q];
    uint32_t cAl0 = al0[q],   cAl1 = al8[q],   cAl2 = al0[4+q],   cAl3 = al8[4+q];

    for (int s = 0; s < S; ++s){
        int b = s & 1;
        if (s+1 < S){
            cpa16(b ? bdst0 : bdst1, bsrc + (size_t)(s+1)*32);
            cpa_commit();
            cpa_wait1();
        } else {
            cpa_wait0();
        }
        __syncthreads();
        int sn = (s+1 < S) ? s+1 : s;
        int i0 = sn*8 + q, i1 = sn*8 + 4 + q;
        uint32_t nAh0 = ah0[i0], nAh1 = ah8[i0], nAh2 = ah0[i1], nAh3 = ah8[i1];
        uint32_t nAl0 = al0[i0], nAl1 = al8[i0], nAl2 = al0[i1], nAl3 = al8[i1];
        #pragma unroll
        for (int tt = 0; tt < 8; ++tt){
            uint4 B = Bs[b][tt][lane];
            mma16816(acc[tt], cAh0,cAh1,cAh2,cAh3, B.x, B.y);
            mma16816(acc[tt], cAh0,cAh1,cAh2,cAh3, B.z, B.w);
            mma16816(acc[tt], cAl0,cAl1,cAl2,cAl3, B.x, B.y);
        }
        __syncthreads();
        cAh0=nAh0; cAh1=nAh1; cAh2=nAh2; cAh3=nAh3;
        cAl0=nAl0; cAl1=nAl1; cAl2=nAl2; cAl3=nAl3;
    }

    bool sel1 = (wset && z == 1);
    float* Cout = sel1 ? Cout1 : Cout0;
    const float* bias = sel1 ? bias1 : bias0;
    const float* eW   = sel1 ? eW1   : eW0;
    const float* eWu  = eW ? eW : eW0;
    int which = wset ? z : 0;
    int crow0 = wset ? row0 : z*Mr + row0;
    int crow8 = wset ? row8 : z*Mr + row8;
    bool hasEpi = (eW0 != nullptr) || (eW1 != nullptr);
    const float *ev0 = 0, *ev8 = 0;
    if (hasEpi){
        ev0 = eWu + ((size_t)((crow0 >> 9)*NE_ + hts[crow0*2 + which]))*DD;
        ev8 = eWu + ((size_t)((crow8 >> 9)*NE_ + hts[crow8*2 + which]))*DD;
    }
    int nbase = nt0*8;
    #pragma unroll
    for (int tt = 0; tt < 8; ++tt){
        int n0 = nbase + tt*8 + q*2;
        float v0 = acc[tt][0], v1 = acc[tt][1], v2 = acc[tt][2], v3 = acc[tt][3];
        if (hasEpi){
            v0 = tanhf(v0 + ev0[n0]   + bias[n0]);
            v1 = tanhf(v1 + ev0[n0+1] + bias[n0+1]);
            v2 = tanhf(v2 + ev8[n0]   + bias[n0]);
            v3 = tanhf(v3 + ev8[n0+1] + bias[n0+1]);
        }
        if (Cout){
            if (row0 < Mr) *(float2*)&Cout[(size_t)crow0*DD + n0] = make_float2(v0, v1);
            if (row8 < Mr) *(float2*)&Cout[(size_t)crow8*DD + n0] = make_float2(v2, v3);
        } else {
            uint32_t lo0, lo8;
            uint32_t hi0 = pack_split(v0, v1, lo0);
            uint32_t hi8 = pack_split(v2, v3, lo8);
            if (row0 < Mr){
                CpHi[(size_t)crow0*(DD/2) + (n0>>1)] = hi0;
                CpLo[(size_t)crow0*(DD/2) + (n0>>1)] = lo0;
            }
            if (row8 < Mr){
                CpHi[(size_t)crow8*(DD/2) + (n0>>1)] = hi8;
                CpLo[(size_t)crow8*(DD/2) + (n0>>1)] = lo8;
            }
        }
    }
}

// ---------------- prep: W_bi -> per-thread mma B fragments ------------------
__global__ void __launch_bounds__(128) k_prepW(const float* __restrict__ Wbi){
    int bid = blockIdx.x;
    int g = bid >> 8, s = bid & 255;
    __shared__ float w_sh[16][104];
    int tid = threadIdx.x;
    for (int idx = tid; idx < 16*104; idx += 128){
        int r = idx / 104, n = idx - r*104;
        w_sh[r][n] = (n < NL_) ? Wbi[(size_t)(g*4096 + s*16 + r)*NL_ + n] : 0.f;
    }
    __syncthreads();
    for (int e = tid; e < NT_*32; e += 128){
        int t = e >> 5, lane = e & 31;
        int gid = lane >> 2, q = lane & 3;
        int n = t*8 + gid;
        int k0 = q*2;
        float w0 = w_sh[k0][n],   w1 = w_sh[k0+1][n];
        float w2 = w_sh[k0+8][n], w3 = w_sh[k0+9][n];
        uint4 F; uint32_t l0, l1;
        F.x = pack_split(w0, w1, l0);
        F.y = pack_split(w2, w3, l1);
        F.z = l0; F.w = l1;
        g_Wfrag[(((size_t)g*256 + s)*NT_ + t)*32 + lane] = F;
    }
}

// ---------------- HMMA bilinear v2: 128 pairs/CTA, SMEM-staged B ------------
// grid (16, 12) = 192 CTAs (one wave at 2/SM). 8 warps = 8 m16 row-blocks;
// each warp computes all 13 n-tiles. B double-buffered via cp.async.
#define BI_SMEM (2*128*65*4 + 2*NT_*32*16)
__global__ void __launch_bounds__(256,2) k_bilinear(){
    extern __shared__ __align__(16) char smc[];
    float* zs_sh = (float*)smc;                       // [128][65]
    float* zo_sh = zs_sh + 128*65;
    uint4* Bsm   = (uint4*)(zo_sh + 128*65);          // [2][NT_*32]
    int tid = threadIdx.x, lane = tid & 31, wid = tid >> 5;
    int g  = blockIdx.y;
    int p0 = blockIdx.x * 128;

    const uint4* src = g_Wfrag + ((size_t)g*256)*NT_*32;
    // prologue: stage s=0 B
    for (int e = tid; e < NT_*32; e += 256) cpa16(Bsm + e, src + e);
    cpa_commit();

    for (int idx = tid; idx < 128*16; idx += 256){
        int p = idx >> 4, c4 = idx & 15;
        float4 vs = *(const float4*)(g_zs + (size_t)(p0+p)*DD + g*64 + c4*4);
        float4 vo = *(const float4*)(g_zo + (size_t)(p0+p)*DD + g*64 + c4*4);
        zs_sh[p*65 + c4*4+0] = vs.x; zs_sh[p*65 + c4*4+1] = vs.y;
        zs_sh[p*65 + c4*4+2] = vs.z; zs_sh[p*65 + c4*4+3] = vs.w;
        zo_sh[p*65 + c4*4+0] = vo.x; zo_sh[p*65 + c4*4+1] = vo.y;
        zo_sh[p*65 + c4*4+2] = vo.z; zo_sh[p*65 + c4*4+3] = vo.w;
    }
    __syncthreads();

    int gid = lane >> 2, q = lane & 3;
    int r0 = wid*16 + gid, r8 = r0 + 8;

    float acc[NT_][4];
    #pragma unroll
    for (int tt = 0; tt < NT_; ++tt){
        acc[tt][0]=0.f; acc[tt][1]=0.f; acc[tt][2]=0.f; acc[tt][3]=0.f;
    }

    for (int s = 0; s < 256; ++s){
        int b = s & 1;
        if (s+1 < 256){
            const uint4* sn = src + (size_t)(s+1)*(NT_*32);
            uint4* dst = Bsm + (b^1)*(NT_*32);
            for (int e = tid; e < NT_*32; e += 256) cpa16(dst + e, sn + e);
            cpa_commit();
            cpa_wait1();
        } else {
            cpa_wait0();
        }
        __syncthreads();

        int i  = s >> 2;
        int c0 = ((s & 3) << 4) + q*2;
        float zr0 = zs_sh[r0*65 + i], zr8 = zs_sh[r8*65 + i];
        float o00 = zo_sh[r0*65 + c0],   o01 = zo_sh[r0*65 + c0+1];
        float o08 = zo_sh[r0*65 + c0+8], o09 = zo_sh[r0*65 + c0+9];
        float o80 = zo_sh[r8*65 + c0],   o81 = zo_sh[r8*65 + c0+1];
        float o88 = zo_sh[r8*65 + c0+8], o89 = zo_sh[r8*65 + c0+9];
        uint32_t al0, al1, al2, al3;
        uint32_t ah0 = pack_split(zr0*o00, zr0*o01, al0);
        uint32_t ah1 = pack_split(zr8*o80, zr8*o81, al1);
        uint32_t ah2 = pack_split(zr0*o08, zr0*o09, al2);
        uint32_t ah3 = pack_split(zr8*o88, zr8*o89, al3);

        const uint4* bb = Bsm + b*(NT_*32);
        #pragma unroll
        for (int tt = 0; tt < NT_; ++tt){
            uint4 B = bb[tt*32 + lane];
            mma16816(acc[tt], ah0, ah1, ah2, ah3, B.x, B.y);   // hi*hi
            mma16816(acc[tt], ah0, ah1, ah2, ah3, B.z, B.w);   // hi*lo
            mma16816(acc[tt], al0, al1, al2, al3, B.x, B.y);   // lo*hi
        }
        __syncthreads();
    }

    int row0g = p0 + r0, row8g = p0 + r8;
    #pragma unroll
    for (int tt = 0; tt < NT_; ++tt){
        int n0 = tt*8 + q*2;
        if (n0 < NL_){
            g_part[g][(size_t)row0g*NL_ + n0] = acc[tt][0];
            g_part[g][(size_t)row8g*NL_ + n0] = acc[tt][2];
        }
        if (n0 + 1 < NL_){
            g_part[g][(size_t)row0g*NL_ + n0+1] = acc[tt][1];
            g_part[g][(size_t)row8g*NL_ + n0+1] = acc[tt][3];
        }
    }
}

// ---------------- finish: sum 12 partials + bias ----------------------------
__global__ void k_finish(float* __restrict__ out, const float* __restrict__ b_bi){
    int i = blockIdx.x*blockDim.x + threadIdx.x;
    if (i < BB*PP*NL_){
        float s = b_bi[i % NL_];
        #pragma unroll
        for (int q = 0; q < NG_; ++q) s += g_part[q][i];
        out[i] = s;
    }
}

// ---------------- launch ----------------------------------------------------
extern "C" void kernel_launch(void* const* d_in, const int* in_sizes, int n_in,
                              void* d_out, int out_size){
    const float* seq  = (const float*)d_in[0];
    const float* att  = (const float*)d_in[1];
    const int*   mpos = (const int*)  d_in[2];
    const int*   hts  = (const int*)  d_in[3];
    const float* Wh   = (const float*)d_in[4];
    const float* bh   = (const float*)d_in[5];
    const float* Wt   = (const float*)d_in[6];
    const float* bt   = (const float*)d_in[7];
    const float* Wbi  = (const float*)d_in[8];
    const float* bbi  = (const float*)d_in[9];
    float* out = (float*)d_out;

    float *p_hsW, *p_tsW, *p_zs, *p_zo;
    uint32_t *p_eHi, *p_eLo, *p_wnHi, *p_wnLo, *p_rsHi, *p_rsLo;
    uint4 *p_seqF, *p_W1hF, *p_W1tF, *p_W2hF, *p_W2tF;
    cudaGetSymbolAddress((void**)&p_hsW,  g_hsW);
    cudaGetSymbolAddress((void**)&p_tsW,  g_tsW);
    cudaGetSymbolAddress((void**)&p_zs,   g_zs);
    cudaGetSymbolAddress((void**)&p_zo,   g_zo);
    cudaGetSymbolAddress((void**)&p_eHi,  g_eHi);
    cudaGetSymbolAddress((void**)&p_eLo,  g_eLo);
    cudaGetSymbolAddress((void**)&p_wnHi, g_wnHi);
    cudaGetSymbolAddress((void**)&p_wnLo, g_wnLo);
    cudaGetSymbolAddress((void**)&p_rsHi, g_rsHi);
    cudaGetSymbolAddress((void**)&p_rsLo, g_rsLo);
    cudaGetSymbolAddress((void**)&p_seqF, g_seqF);
    cudaGetSymbolAddress((void**)&p_W1hF, g_W1hF);
    cudaGetSymbolAddress((void**)&p_W1tF, g_W1tF);
    cudaGetSymbolAddress((void**)&p_W2hF, g_W2hF);
    cudaGetSymbolAddress((void**)&p_W2tF, g_W2tF);

    static bool attr_done = false;
    if (!attr_done){
        cudaFuncSetAttribute(k_bilinear, cudaFuncAttributeMaxDynamicSharedMemorySize, BI_SMEM);
        attr_done = true;
    }

    // operand prep
    k_prepW<<<NG_*256, 128>>>(Wbi);
    k_packB<<<dim3(64, BB), 256>>>(seq, (long)LLEN*DD, p_seqF, (long)96*64*32, 64);
    k_packW<<<dim3(48, 4), 256>>>(Wh, Wt, p_W1hF, p_W1tF, p_W2hF, p_W2tF);

    k_ent_emb<<<BB*NE_, 256>>>(seq, mpos);
    k_ent_att<<<BB*NE_*HH, 256>>>(att, mpos);

    // hsW / tsW : [168,768] = E @ W1{h,t}
    k_hgemm2<<<dim3(12, 2, 2), 256>>>(p_eHi, p_eLo, 0,
                                      p_W1hF, p_W1tF, 0,
                                      p_hsW, p_tsW, nullptr, nullptr,
                                      BB*NE_, 48, 1,
                                      nullptr, nullptr, nullptr, nullptr, nullptr);

    k_pairw<<<BB*PP, 256>>>(hts);

    // rs : per-doc [512,1024]@[1024,768] -> split pairs
    k_hgemm2<<<dim3(12, 4, BB), 256>>>(p_wnHi, p_wnLo, (long)PP*(LLEN/2),
                                       p_seqF, nullptr, (long)96*64*32,
                                       nullptr, nullptr, p_rsHi, p_rsLo,
                                       PP, 64, 0,
                                       nullptr, nullptr, nullptr, nullptr, nullptr);

    // zs / zo : [2048,768]@[768,768] + gather + bias + tanh
    k_hgemm2<<<dim3(12, 16, 2), 256>>>(p_rsHi, p_rsLo, 0,
                                       p_W2hF, p_W2tF, 0,
                                       p_zs, p_zo, nullptr, nullptr,
                                       BB*PP, 48, 1,
                                       bh, bt, p_hsW, p_tsW, hts);

    k_bilinear<<<dim3(16, NG_), 256, BI_SMEM>>>();
    k_finish<<<(BB*PP*NL_ + 255)/256, 256>>>(out, bbi);
}